// round 1
// baseline (speedup 1.0000x reference)
#include <cuda_runtime.h>
#include <cstdint>
#include <cstddef>

#define BATCH 4
#define HEADS 16
#define SEQ   2048
#define DIM   64
#define NBH   (BATCH*HEADS)
#define N_ITERS 40

// ---------------- f32x2 packed helpers (sm_100+) ----------------
__device__ __forceinline__ void ffma2(unsigned long long& c, unsigned long long a, unsigned long long b){
    asm("fma.rn.f32x2 %0, %1, %2, %3;" : "=l"(c) : "l"(a), "l"(b), "l"(c));
}
__device__ __forceinline__ unsigned long long pack2(float x, float y){
    unsigned long long r;
    asm("mov.b64 %0, {%1, %2};" : "=l"(r) : "f"(x), "f"(y));
    return r;
}
__device__ __forceinline__ void unpack2(unsigned long long d, float& x, float& y){
    asm("mov.b64 {%0, %1}, %2;" : "=f"(x), "=f"(y) : "l"(d));
}

// ================================================================
// Kernel 1: Xa[bh,q,k] = (sum_d Q[bh,q,d]*K[bh,k,d]) * (1/8) * (alpha-1)
// 128x128 output tile per CTA, K-dim = 64 (full). f32x2 FFMA.
// ================================================================
__global__ __launch_bounds__(256) void qk_kernel(const float* __restrict__ Q,
                                                 const float* __restrict__ Km,
                                                 const float* __restrict__ alpha_p,
                                                 float* __restrict__ P)
{
    extern __shared__ float sm[];
    float* Qs = sm;              // [64][128] : Qs[d*128 + m]
    float* Ks = sm + 64*128;     // [64][128] : Ks[d*128 + n]

    const int bh = blockIdx.z;
    const int q0 = blockIdx.y * 128;
    const int k0 = blockIdx.x * 128;
    const float* Qb = Q  + (size_t)bh * SEQ * DIM;
    const float* Kb = Km + (size_t)bh * SEQ * DIM;
    const int tid = threadIdx.x;

    // cooperative load + transpose of Q/K tiles (128 rows x 64 d each)
    for (int i = tid; i < 128*16; i += 256){
        int row = i >> 4;
        int c4  = (i & 15) << 2;
        float4 v = *(const float4*)(Qb + (size_t)(q0 + row) * DIM + c4);
        Qs[(c4+0)*128 + row] = v.x;
        Qs[(c4+1)*128 + row] = v.y;
        Qs[(c4+2)*128 + row] = v.z;
        Qs[(c4+3)*128 + row] = v.w;
        float4 w = *(const float4*)(Kb + (size_t)(k0 + row) * DIM + c4);
        Ks[(c4+0)*128 + row] = w.x;
        Ks[(c4+1)*128 + row] = w.y;
        Ks[(c4+2)*128 + row] = w.z;
        Ks[(c4+3)*128 + row] = w.w;
    }
    __syncthreads();

    const int tx = tid & 15, ty = tid >> 4;
    const int m0 = ty << 3;              // 8 consecutive rows
    // columns: split fragments tx*4 and 64+tx*4 (conflict-free LDS.64)
    unsigned long long c2[8][4];
    #pragma unroll
    for (int i = 0; i < 8; i++)
        #pragma unroll
        for (int j = 0; j < 4; j++) c2[i][j] = 0ULL;

    #pragma unroll 8
    for (int kk = 0; kk < 64; kk++){
        const float4* qv = (const float4*)(Qs + kk*128 + m0);
        float4 a0 = qv[0], a1 = qv[1];
        const unsigned long long* kv0 = (const unsigned long long*)(Ks + kk*128);
        const unsigned long long* kv1 = (const unsigned long long*)(Ks + kk*128 + 64);
        unsigned long long b0 = kv0[tx*2], b1 = kv0[tx*2+1];
        unsigned long long b2 = kv1[tx*2], b3 = kv1[tx*2+1];
        float a[8] = {a0.x,a0.y,a0.z,a0.w,a1.x,a1.y,a1.z,a1.w};
        #pragma unroll
        for (int i = 0; i < 8; i++){
            unsigned long long aa = pack2(a[i], a[i]);
            ffma2(c2[i][0], aa, b0);
            ffma2(c2[i][1], aa, b1);
            ffma2(c2[i][2], aa, b2);
            ffma2(c2[i][3], aa, b3);
        }
    }

    const float sc = (alpha_p[0] - 1.0f) * 0.125f;  // scale = 1/sqrt(64), times (alpha-1)
    #pragma unroll
    for (int i = 0; i < 8; i++){
        float o[8];
        #pragma unroll
        for (int j = 0; j < 4; j++) unpack2(c2[i][j], o[2*j], o[2*j+1]);
        float* rowp = P + ((size_t)bh * SEQ + q0 + m0 + i) * SEQ + k0;
        float4 w0 = make_float4(o[0]*sc, o[1]*sc, o[2]*sc, o[3]*sc);
        float4 w1 = make_float4(o[4]*sc, o[5]*sc, o[6]*sc, o[7]*sc);
        *(float4*)(rowp + tx*4)      = w0;
        *(float4*)(rowp + 64 + tx*4) = w1;
    }
}

// ================================================================
// Kernel 2: per-row entmax bisection (compacted) + sparse PV
// one 256-thread block per query row (131072 blocks)
// ================================================================
template<bool SQ>
__device__ __forceinline__ float pf(float r, float inv){
    return SQ ? r * r : __powf(r, inv);
}

__device__ __forceinline__ float blockReduceSum(float v, float* sred, int t){
    #pragma unroll
    for (int o = 16; o; o >>= 1) v += __shfl_xor_sync(0xffffffffu, v, o);
    if ((t & 31) == 0) sred[t >> 5] = v;
    __syncthreads();
    if (t < 32){
        float x = (t < 8) ? sred[t] : 0.0f;
        #pragma unroll
        for (int o = 4; o; o >>= 1) x += __shfl_xor_sync(0xffffffffu, x, o);
        if (t == 0) sred[8] = x;
    }
    __syncthreads();
    float r = sred[8];
    __syncthreads();
    return r;
}

__device__ __forceinline__ float blockReduceMax(float v, float* sred, int t){
    #pragma unroll
    for (int o = 16; o; o >>= 1) v = fmaxf(v, __shfl_xor_sync(0xffffffffu, v, o));
    if ((t & 31) == 0) sred[t >> 5] = v;
    __syncthreads();
    if (t < 32){
        float x = (t < 8) ? sred[t] : __int_as_float(0xff800000);
        #pragma unroll
        for (int o = 4; o; o >>= 1) x = fmaxf(x, __shfl_xor_sync(0xffffffffu, x, o));
        if (t == 0) sred[8] = x;
    }
    __syncthreads();
    float r = sred[8];
    __syncthreads();
    return r;
}

template<bool SQ>
__device__ __forceinline__ void entmax_body(float* prow, const float* Vb,
        float* __restrict__ out, int row, int t, float am1, float inv,
        float* sval, int* sidx, float* sred, float (*sout)[64], int* scnt)
{
    float xa[8];
    {
        float4 v0 = *(const float4*)(prow + t*8);
        float4 v1 = *(const float4*)(prow + t*8 + 4);
        xa[0]=v0.x; xa[1]=v0.y; xa[2]=v0.z; xa[3]=v0.w;
        xa[4]=v1.x; xa[5]=v1.y; xa[6]=v1.z; xa[7]=v1.w;
    }
    float m = xa[0];
    #pragma unroll
    for (int j = 1; j < 8; j++) m = fmaxf(m, xa[j]);
    m = blockReduceMax(m, sred, t);

    float tau    = m - 1.0f;                               // tau_lo
    float tau_hi = m - powf(1.0f / (float)SEQ, am1);
    float dm     = tau_hi - tau;

    if (t == 0) *scnt = 0;
    __syncthreads();
    // compact: elements with Xa <= max-1 are permanently zero (tau never decreases)
    #pragma unroll
    for (int j = 0; j < 8; j++){
        if (xa[j] > tau){
            int p = atomicAdd(scnt, 1);
            sval[p] = xa[j];
            sidx[p] = t*8 + j;
        }
    }
    __syncthreads();
    const int A = *scnt;

    float fl = 0.0f;
    for (int i = t; i < A; i += 256){
        float r = fmaxf(sval[i] - tau, 0.0f);
        fl += pf<SQ>(r, inv);
    }
    const float f_lo = blockReduceSum(fl, sred, t) - 1.0f;

    for (int it = 0; it < N_ITERS; it++){
        dm *= 0.5f;
        float tau_m = tau + dm;
        float fm = 0.0f;
        for (int i = t; i < A; i += 256){
            float r = fmaxf(sval[i] - tau_m, 0.0f);
            fm += pf<SQ>(r, inv);
        }
        float f_m = blockReduceSum(fm, sred, t) - 1.0f;
        if (f_m * f_lo >= 0.0f) tau = tau_m;
    }

    float sp = 0.0f;
    for (int i = t; i < A; i += 256){
        float r = fmaxf(sval[i] - tau, 0.0f);
        sp += pf<SQ>(r, inv);
    }
    float ssum = blockReduceSum(sp, sred, t);
    float isum = 1.0f / ssum;

    // write normalized p over the full row (in place over Xa)
    float pj[8];
    #pragma unroll
    for (int j = 0; j < 8; j++){
        float r = fmaxf(xa[j] - tau, 0.0f);
        pj[j] = pf<SQ>(r, inv) * isum;
    }
    *(float4*)(prow + t*8)     = make_float4(pj[0], pj[1], pj[2], pj[3]);
    *(float4*)(prow + t*8 + 4) = make_float4(pj[4], pj[5], pj[6], pj[7]);

    // sparse PV: out[row, :] = sum over active k of p_k * V[k, :]
    int d = t & 63, g = t >> 6;
    float acc = 0.0f;
    for (int i = g; i < A; i += 4){
        float r = fmaxf(sval[i] - tau, 0.0f);
        float p = pf<SQ>(r, inv) * isum;
        acc += p * Vb[(size_t)sidx[i] * DIM + d];
    }
    sout[g][d] = acc;
    __syncthreads();
    if (t < 64){
        out[(size_t)row * DIM + t] = sout[0][t] + sout[1][t] + sout[2][t] + sout[3][t];
    }
}

__global__ __launch_bounds__(256) void entmax_pv_kernel(const float* __restrict__ V,
        const float* __restrict__ alpha_p, float* __restrict__ out, float* __restrict__ P)
{
    __shared__ float sval[2048];
    __shared__ int   sidx[2048];
    __shared__ float sred[12];
    __shared__ float sout[4][64];
    __shared__ int   scnt;

    const int row = blockIdx.x;
    const int bh  = row >> 11;
    const int t   = threadIdx.x;
    float* prow = P + (size_t)row * SEQ;
    const float* Vb = V + (size_t)bh * SEQ * DIM;

    const float am1 = alpha_p[0] - 1.0f;
    const float inv = 1.0f / am1;
    const bool sq = fabsf(inv - 2.0f) < 1e-6f;   // alpha == 1.5 fast path

    if (sq) entmax_body<true >(prow, Vb, out, row, t, am1, inv, sval, sidx, sred, sout, &scnt);
    else    entmax_body<false>(prow, Vb, out, row, t, am1, inv, sval, sidx, sred, sout, &scnt);
}

// ================================================================
extern "C" void kernel_launch(void* const* d_in, const int* in_sizes, int n_in,
                              void* d_out, int out_size)
{
    const float* Q     = (const float*)d_in[0];
    const float* K     = (const float*)d_in[1];
    const float* V     = (const float*)d_in[2];
    const float* alpha = (const float*)d_in[3];

    float* out = (float*)d_out;                              // [B,H,S,D]
    float* P   = out + (size_t)NBH * SEQ * DIM;              // [B,H,S,S]

    cudaFuncSetAttribute(qk_kernel, cudaFuncAttributeMaxDynamicSharedMemorySize, 65536);

    dim3 g1(SEQ/128, SEQ/128, NBH);
    qk_kernel<<<g1, 256, 65536>>>(Q, K, alpha, P);

    entmax_pv_kernel<<<NBH * SEQ, 256>>>(V, alpha, out, P);
}

// round 2
// speedup vs baseline: 2.1839x; 2.1839x over previous
#include <cuda_runtime.h>
#include <cstdint>
#include <cstddef>

#define BATCH 4
#define HEADS 16
#define SEQ   2048
#define DIM   64
#define NBH   (BATCH*HEADS)
#define N_ITERS 30
#define CAP    512
#define NEG_INF __int_as_float(0xff800000)

// ---------------- f32x2 packed helpers (sm_100+) ----------------
__device__ __forceinline__ void ffma2(unsigned long long& c, unsigned long long a, unsigned long long b){
    asm("fma.rn.f32x2 %0, %1, %2, %3;" : "=l"(c) : "l"(a), "l"(b), "l"(c));
}
__device__ __forceinline__ unsigned long long pack2(float x, float y){
    unsigned long long r;
    asm("mov.b64 %0, {%1, %2};" : "=l"(r) : "f"(x), "f"(y));
    return r;
}
__device__ __forceinline__ void unpack2(unsigned long long d, float& x, float& y){
    asm("mov.b64 {%0, %1}, %2;" : "=f"(x), "=f"(y) : "l"(d));
}

// ================================================================
// Kernel 1: Xa[bh,q,k] = (sum_d Q[bh,q,d]*K[bh,k,d]) * (1/8) * (alpha-1)
// ================================================================
__global__ __launch_bounds__(256) void qk_kernel(const float* __restrict__ Q,
                                                 const float* __restrict__ Km,
                                                 const float* __restrict__ alpha_p,
                                                 float* __restrict__ P)
{
    extern __shared__ float sm[];
    float* Qs = sm;              // [64][128]
    float* Ks = sm + 64*128;     // [64][128]

    const int bh = blockIdx.z;
    const int q0 = blockIdx.y * 128;
    const int k0 = blockIdx.x * 128;
    const float* Qb = Q  + (size_t)bh * SEQ * DIM;
    const float* Kb = Km + (size_t)bh * SEQ * DIM;
    const int tid = threadIdx.x;

    for (int i = tid; i < 128*16; i += 256){
        int row = i >> 4;
        int c4  = (i & 15) << 2;
        float4 v = *(const float4*)(Qb + (size_t)(q0 + row) * DIM + c4);
        Qs[(c4+0)*128 + row] = v.x;
        Qs[(c4+1)*128 + row] = v.y;
        Qs[(c4+2)*128 + row] = v.z;
        Qs[(c4+3)*128 + row] = v.w;
        float4 w = *(const float4*)(Kb + (size_t)(k0 + row) * DIM + c4);
        Ks[(c4+0)*128 + row] = w.x;
        Ks[(c4+1)*128 + row] = w.y;
        Ks[(c4+2)*128 + row] = w.z;
        Ks[(c4+3)*128 + row] = w.w;
    }
    __syncthreads();

    const int tx = tid & 15, ty = tid >> 4;
    const int m0 = ty << 3;
    unsigned long long c2[8][4];
    #pragma unroll
    for (int i = 0; i < 8; i++)
        #pragma unroll
        for (int j = 0; j < 4; j++) c2[i][j] = 0ULL;

    #pragma unroll 8
    for (int kk = 0; kk < 64; kk++){
        const float4* qv = (const float4*)(Qs + kk*128 + m0);
        float4 a0 = qv[0], a1 = qv[1];
        const unsigned long long* kv0 = (const unsigned long long*)(Ks + kk*128);
        const unsigned long long* kv1 = (const unsigned long long*)(Ks + kk*128 + 64);
        unsigned long long b0 = kv0[tx*2], b1 = kv0[tx*2+1];
        unsigned long long b2 = kv1[tx*2], b3 = kv1[tx*2+1];
        float a[8] = {a0.x,a0.y,a0.z,a0.w,a1.x,a1.y,a1.z,a1.w};
        #pragma unroll
        for (int i = 0; i < 8; i++){
            unsigned long long aa = pack2(a[i], a[i]);
            ffma2(c2[i][0], aa, b0);
            ffma2(c2[i][1], aa, b1);
            ffma2(c2[i][2], aa, b2);
            ffma2(c2[i][3], aa, b3);
        }
    }

    const float sc = (alpha_p[0] - 1.0f) * 0.125f;
    #pragma unroll
    for (int i = 0; i < 8; i++){
        float o[8];
        #pragma unroll
        for (int j = 0; j < 4; j++) unpack2(c2[i][j], o[2*j], o[2*j+1]);
        float* rowp = P + ((size_t)bh * SEQ + q0 + m0 + i) * SEQ + k0;
        float4 w0 = make_float4(o[0]*sc, o[1]*sc, o[2]*sc, o[3]*sc);
        float4 w1 = make_float4(o[4]*sc, o[5]*sc, o[6]*sc, o[7]*sc);
        *(float4*)(rowp + tx*4)      = w0;
        *(float4*)(rowp + 64 + tx*4) = w1;
    }
}

// ================================================================
// Kernel 2 v2: one WARP per row. shfl-only reductions, compaction,
// zero-fill + scatter, sparse PV.
// ================================================================
template<bool SQ>
__device__ __forceinline__ float pf(float r, float inv){
    return SQ ? r * r : __powf(r, inv);
}

__device__ __forceinline__ float wredmax(float v){
    #pragma unroll
    for (int o = 16; o; o >>= 1) v = fmaxf(v, __shfl_xor_sync(0xffffffffu, v, o));
    return v;
}
__device__ __forceinline__ float wredsum(float v){
    #pragma unroll
    for (int o = 16; o; o >>= 1) v += __shfl_xor_sync(0xffffffffu, v, o);
    return v;
}

template<bool SQ>
__device__ __forceinline__ void row_body(float* __restrict__ prow,
                                         const float* __restrict__ Vb,
                                         float* __restrict__ outrow,
                                         float am1, float inv,
                                         float* __restrict__ sval,
                                         int*   __restrict__ sidx,
                                         int l)
{
    // ---- pass 1: row max ----
    const float4* prow4 = (const float4*)prow;
    float m = NEG_INF;
    #pragma unroll
    for (int c = 0; c < 16; c++){
        float4 v = prow4[c*32 + l];
        m = fmaxf(m, fmaxf(fmaxf(v.x, v.y), fmaxf(v.z, v.w)));
    }
    m = wredmax(m);

    float tau        = m - 1.0f;                       // tau_lo
    const float t_hi = m - powf(1.0f/(float)SEQ, am1);
    float dm         = t_hi - tau;

    // ---- pass 2: compact actives (Xa > max-1); rest are permanently p=0 ----
    int A = 0;
    for (int j = l; j < SEQ; j += 32){
        float v  = prow[j];
        bool act = v > tau;
        unsigned mk = __ballot_sync(0xffffffffu, act);
        if (act){
            int pos = A + __popc(mk & ((1u << l) - 1u));
            if (pos < CAP){ sval[pos] = v; sidx[pos] = j; }
        }
        A += __popc(mk);
    }
    __syncwarp();

    if (A <= CAP){
        // zero the full row now; latency hidden behind bisection
        float4 z = make_float4(0.f, 0.f, 0.f, 0.f);
        float4* pw = (float4*)prow;
        #pragma unroll
        for (int c = 0; c < 16; c++) pw[c*32 + l] = z;

        float isum;
        if (A <= 128){
            // register-resident actives (<=4 per lane)
            float v0 = (l      < A) ? sval[l     ] : NEG_INF;
            float v1 = (l + 32 < A) ? sval[l + 32] : NEG_INF;
            float v2 = (l + 64 < A) ? sval[l + 64] : NEG_INF;
            float v3 = (l + 96 < A) ? sval[l + 96] : NEG_INF;

            float r0 = fmaxf(v0 - tau, 0.f), r1 = fmaxf(v1 - tau, 0.f);
            float r2 = fmaxf(v2 - tau, 0.f), r3 = fmaxf(v3 - tau, 0.f);
            float f_lo = wredsum(pf<SQ>(r0,inv) + pf<SQ>(r1,inv) +
                                 pf<SQ>(r2,inv) + pf<SQ>(r3,inv)) - 1.0f;

            for (int it = 0; it < N_ITERS; it++){
                dm *= 0.5f;
                float tm = tau + dm;
                float a0 = fmaxf(v0 - tm, 0.f), a1 = fmaxf(v1 - tm, 0.f);
                float a2 = fmaxf(v2 - tm, 0.f), a3 = fmaxf(v3 - tm, 0.f);
                float fm = wredsum(pf<SQ>(a0,inv) + pf<SQ>(a1,inv) +
                                   pf<SQ>(a2,inv) + pf<SQ>(a3,inv)) - 1.0f;
                if (fm * f_lo >= 0.0f) tau = tm;
            }
            float a0 = fmaxf(v0 - tau, 0.f), a1 = fmaxf(v1 - tau, 0.f);
            float a2 = fmaxf(v2 - tau, 0.f), a3 = fmaxf(v3 - tau, 0.f);
            float ss = wredsum(pf<SQ>(a0,inv) + pf<SQ>(a1,inv) +
                               pf<SQ>(a2,inv) + pf<SQ>(a3,inv));
            isum = 1.0f / ss;
        } else {
            // smem-resident actives (128 < A <= 512)
            float fl = 0.f;
            for (int i = l; i < A; i += 32)
                fl += pf<SQ>(fmaxf(sval[i] - tau, 0.f), inv);
            float f_lo = wredsum(fl) - 1.0f;

            for (int it = 0; it < N_ITERS; it++){
                dm *= 0.5f;
                float tm = tau + dm;
                float fm = 0.f;
                for (int i = l; i < A; i += 32)
                    fm += pf<SQ>(fmaxf(sval[i] - tm, 0.f), inv);
                fm = wredsum(fm) - 1.0f;
                if (fm * f_lo >= 0.0f) tau = tm;
            }
            float ss = 0.f;
            for (int i = l; i < A; i += 32)
                ss += pf<SQ>(fmaxf(sval[i] - tau, 0.f), inv);
            isum = 1.0f / wredsum(ss);
        }

        __syncwarp();   // zero-fill stores ordered before scatter
        // ---- scatter normalized p over support ----
        for (int i = l; i < A; i += 32){
            float r = sval[i] - tau;
            if (r > 0.0f) prow[sidx[i]] = pf<SQ>(r, inv) * isum;
        }

        // ---- sparse PV: out = sum_{support} p_k * V[k,:], 2 dims per lane ----
        float ax = 0.f, ay = 0.f;
        #pragma unroll 2
        for (int i = 0; i < A; i++){
            float r = sval[i] - tau;              // LDS broadcast
            if (r > 0.0f){
                float p = pf<SQ>(r, inv) * isum;
                float2 vv = *(const float2*)(Vb + (size_t)sidx[i]*DIM + 2*l);
                ax += p * vv.x; ay += p * vv.y;
            }
        }
        *(float2*)(outrow + 2*l) = make_float2(ax, ay);
    } else {
        // -------- rare overflow fallback: bisect directly over gmem row --------
        float fl = 0.f;
        for (int j = l; j < SEQ; j += 32)
            fl += pf<SQ>(fmaxf(prow[j] - tau, 0.f), inv);
        float f_lo = wredsum(fl) - 1.0f;

        for (int it = 0; it < N_ITERS; it++){
            dm *= 0.5f;
            float tm = tau + dm;
            float fm = 0.f;
            for (int j = l; j < SEQ; j += 32)
                fm += pf<SQ>(fmaxf(prow[j] - tm, 0.f), inv);
            fm = wredsum(fm) - 1.0f;
            if (fm * f_lo >= 0.0f) tau = tm;
        }
        float ss = 0.f;
        for (int j = l; j < SEQ; j += 32)
            ss += pf<SQ>(fmaxf(prow[j] - tau, 0.f), inv);
        float isum = 1.0f / wredsum(ss);

        for (int j = l; j < SEQ; j += 32){
            float r = fmaxf(prow[j] - tau, 0.f);
            prow[j] = pf<SQ>(r, inv) * isum;
        }
        __syncwarp();
        float ax = 0.f, ay = 0.f;
        for (int k = 0; k < SEQ; k++){
            float p = prow[k];
            if (p > 0.0f){
                float2 vv = *(const float2*)(Vb + (size_t)k*DIM + 2*l);
                ax += p * vv.x; ay += p * vv.y;
            }
        }
        *(float2*)(outrow + 2*l) = make_float2(ax, ay);
    }
}

__global__ __launch_bounds__(256) void entmax_pv_warp(const float* __restrict__ V,
        const float* __restrict__ alpha_p, float* __restrict__ out, float* __restrict__ P)
{
    __shared__ float sval[8][CAP];
    __shared__ int   sidx[8][CAP];

    const int w   = threadIdx.x >> 5;
    const int l   = threadIdx.x & 31;
    const int row = blockIdx.x * 8 + w;
    const int bh  = row >> 11;

    float* prow = P + (size_t)row * SEQ;
    const float* Vb = V + (size_t)bh * SEQ * DIM;
    float* outrow = out + (size_t)row * DIM;

    const float am1 = alpha_p[0] - 1.0f;
    const float inv = 1.0f / am1;
    const bool  sq  = fabsf(inv - 2.0f) < 1e-6f;

    if (sq) row_body<true >(prow, Vb, outrow, am1, inv, sval[w], sidx[w], l);
    else    row_body<false>(prow, Vb, outrow, am1, inv, sval[w], sidx[w], l);
}

// ================================================================
extern "C" void kernel_launch(void* const* d_in, const int* in_sizes, int n_in,
                              void* d_out, int out_size)
{
    const float* Q     = (const float*)d_in[0];
    const float* K     = (const float*)d_in[1];
    const float* V     = (const float*)d_in[2];
    const float* alpha = (const float*)d_in[3];

    float* out = (float*)d_out;                              // [B,H,S,D]
    float* P   = out + (size_t)NBH * SEQ * DIM;              // [B,H,S,S]

    cudaFuncSetAttribute(qk_kernel, cudaFuncAttributeMaxDynamicSharedMemorySize, 65536);

    dim3 g1(SEQ/128, SEQ/128, NBH);
    qk_kernel<<<g1, 256, 65536>>>(Q, K, alpha, P);

    entmax_pv_warp<<<(NBH * SEQ) / 8, 256>>>(V, alpha, out, P);
}

// round 3
// speedup vs baseline: 2.6395x; 1.2087x over previous
#include <cuda_runtime.h>
#include <cstdint>
#include <cstddef>

#define BATCH 4
#define HEADS 16
#define SEQ   2048
#define DIM   64
#define NBH   (BATCH*HEADS)
#define CAP    512
#define NEG_INF __int_as_float(0xff800000)

// per-(row, ktile) max scratch: [NBH*SEQ][16]
__device__ float g_tmax[(size_t)NBH * SEQ * 16];

// ---------------- f32x2 packed helpers ----------------
__device__ __forceinline__ void ffma2(unsigned long long& c, unsigned long long a, unsigned long long b){
    asm("fma.rn.f32x2 %0, %1, %2, %3;" : "=l"(c) : "l"(a), "l"(b), "l"(c));
}
__device__ __forceinline__ unsigned long long pack2(float x, float y){
    unsigned long long r;
    asm("mov.b64 %0, {%1, %2};" : "=l"(r) : "f"(x), "f"(y));
    return r;
}
__device__ __forceinline__ void unpack2(unsigned long long d, float& x, float& y){
    asm("mov.b64 {%0, %1}, %2;" : "=f"(x), "=f"(y) : "l"(d));
}

// ================================================================
// Kernel 1: Xa = (QK^T)*scale*(alpha-1), plus per-(row,ktile) max export
// ================================================================
__global__ __launch_bounds__(256) void qk_kernel(const float* __restrict__ Q,
                                                 const float* __restrict__ Km,
                                                 const float* __restrict__ alpha_p,
                                                 float* __restrict__ P)
{
    extern __shared__ float sm[];
    float* Qs = sm;              // [64][128]
    float* Ks = sm + 64*128;     // [64][128]

    const int bh = blockIdx.z;
    const int q0 = blockIdx.y * 128;
    const int k0 = blockIdx.x * 128;
    const float* Qb = Q  + (size_t)bh * SEQ * DIM;
    const float* Kb = Km + (size_t)bh * SEQ * DIM;
    const int tid = threadIdx.x;

    for (int i = tid; i < 128*16; i += 256){
        int row = i >> 4;
        int c4  = (i & 15) << 2;
        float4 v = *(const float4*)(Qb + (size_t)(q0 + row) * DIM + c4);
        Qs[(c4+0)*128 + row] = v.x;
        Qs[(c4+1)*128 + row] = v.y;
        Qs[(c4+2)*128 + row] = v.z;
        Qs[(c4+3)*128 + row] = v.w;
        float4 w = *(const float4*)(Kb + (size_t)(k0 + row) * DIM + c4);
        Ks[(c4+0)*128 + row] = w.x;
        Ks[(c4+1)*128 + row] = w.y;
        Ks[(c4+2)*128 + row] = w.z;
        Ks[(c4+3)*128 + row] = w.w;
    }
    __syncthreads();

    const int tx = tid & 15, ty = tid >> 4;
    const int m0 = ty << 3;
    unsigned long long c2[8][4];
    #pragma unroll
    for (int i = 0; i < 8; i++)
        #pragma unroll
        for (int j = 0; j < 4; j++) c2[i][j] = 0ULL;

    #pragma unroll 8
    for (int kk = 0; kk < 64; kk++){
        const float4* qv = (const float4*)(Qs + kk*128 + m0);
        float4 a0 = qv[0], a1 = qv[1];
        const unsigned long long* kv0 = (const unsigned long long*)(Ks + kk*128);
        const unsigned long long* kv1 = (const unsigned long long*)(Ks + kk*128 + 64);
        unsigned long long b0 = kv0[tx*2], b1 = kv0[tx*2+1];
        unsigned long long b2 = kv1[tx*2], b3 = kv1[tx*2+1];
        float a[8] = {a0.x,a0.y,a0.z,a0.w,a1.x,a1.y,a1.z,a1.w};
        #pragma unroll
        for (int i = 0; i < 8; i++){
            unsigned long long aa = pack2(a[i], a[i]);
            ffma2(c2[i][0], aa, b0);
            ffma2(c2[i][1], aa, b1);
            ffma2(c2[i][2], aa, b2);
            ffma2(c2[i][3], aa, b3);
        }
    }

    const float sc = (alpha_p[0] - 1.0f) * 0.125f;
    #pragma unroll
    for (int i = 0; i < 8; i++){
        float o[8];
        #pragma unroll
        for (int j = 0; j < 4; j++) unpack2(c2[i][j], o[2*j], o[2*j+1]);
        #pragma unroll
        for (int j = 0; j < 8; j++) o[j] *= sc;

        const size_t row = (size_t)bh * SEQ + q0 + m0 + i;
        float* rowp = P + row * SEQ + k0;
        *(float4*)(rowp + tx*4)      = make_float4(o[0], o[1], o[2], o[3]);
        *(float4*)(rowp + 64 + tx*4) = make_float4(o[4], o[5], o[6], o[7]);

        // per-row tile max across the 16 tx lanes (xor<16 stays in half-warp)
        float rm = o[0];
        #pragma unroll
        for (int j = 1; j < 8; j++) rm = fmaxf(rm, o[j]);
        #pragma unroll
        for (int off = 1; off < 16; off <<= 1)
            rm = fmaxf(rm, __shfl_xor_sync(0xffffffffu, rm, off));
        if (tx == 0) g_tmax[row * 16 + blockIdx.x] = rm;
    }
}

// ================================================================
// Kernel 2 v3: warp/row; threshold known up-front; single row pass;
// mid-bisect recompaction; sparse scatter + PV.
// ================================================================
template<bool SQ>
__device__ __forceinline__ float pf(float r, float inv){
    return SQ ? r * r : __powf(r, inv);
}
__device__ __forceinline__ float wredmax(float v){
    #pragma unroll
    for (int o = 16; o; o >>= 1) v = fmaxf(v, __shfl_xor_sync(0xffffffffu, v, o));
    return v;
}
__device__ __forceinline__ float wredsum(float v){
    #pragma unroll
    for (int o = 16; o; o >>= 1) v += __shfl_xor_sync(0xffffffffu, v, o);
    return v;
}

template<bool SQ>
__device__ __forceinline__ void row_body(float* __restrict__ prow,
                                         const float* __restrict__ Vb,
                                         float* __restrict__ outrow,
                                         size_t row, float am1, float inv,
                                         float* __restrict__ sval,
                                         int*   __restrict__ sidx,
                                         int l)
{
    // ---- gmax from K1's tile maxes (64B) ----
    float m = (l < 16) ? g_tmax[row * 16 + l] : NEG_INF;
    m = wredmax(m);

    float tau        = m - 1.0f;                       // tau_lo
    const float t_hi = m - powf(1.0f/(float)SEQ, am1);
    float dm         = t_hi - tau;

    // ---- single pass: read row once (float4), compact actives, accumulate f_lo ----
    const float4* prow4 = (const float4*)prow;
    int A = 0;
    float fl = 0.0f;
    #pragma unroll
    for (int c = 0; c < 16; c++){
        float4 v = prow4[c*32 + l];
        const int jb = (c*32 + l) * 4;
        float vs[4] = {v.x, v.y, v.z, v.w};
        #pragma unroll
        for (int s = 0; s < 4; s++){
            bool act = vs[s] > tau;
            unsigned mk = __ballot_sync(0xffffffffu, act);
            if (act){
                int pos = A + __popc(mk & ((1u << l) - 1u));
                if (pos < CAP){ sval[pos] = vs[s]; sidx[pos] = jb + s; }
                fl += pf<SQ>(vs[s] - tau, inv);
            }
            A += __popc(mk);
        }
    }
    const float f_lo = wredsum(fl) - 1.0f;

    if (A <= CAP){
        // zero the full row now; hidden behind bisection
        float4 z = make_float4(0.f, 0.f, 0.f, 0.f);
        float4* pw = (float4*)prow;
        #pragma unroll
        for (int c = 0; c < 16; c++) pw[c*32 + l] = z;

        // ---- phase 1: 6 iters over full candidate list ----
        #pragma unroll 1
        for (int it = 0; it < 6; it++){
            dm *= 0.5f;
            float tm = tau + dm;
            float fm = 0.f;
            for (int i = l; i < A; i += 32)
                fm += pf<SQ>(fmaxf(sval[i] - tm, 0.f), inv);
            fm = wredsum(fm) - 1.0f;
            if (fm * f_lo >= 0.0f) tau = tm;
        }

        // ---- recompact: tau is monotone increasing, vals <= tau are dead forever ----
        int A2 = 0;
        for (int base = 0; base < A; base += 32){
            int i = base + l;
            float vv = (i < A) ? sval[i] : NEG_INF;
            int   ii = (i < A) ? sidx[i] : 0;
            bool keep = vv > tau;
            unsigned mk = __ballot_sync(0xffffffffu, keep);  // also syncs reads before writes
            if (keep){
                int pos = A2 + __popc(mk & ((1u << l) - 1u));
                sval[pos] = vv; sidx[pos] = ii;
            }
            A2 += __popc(mk);
        }
        A = A2;
        __syncwarp();

        // ---- phase 2: 21 iters over shrunken list (total 27 ≡ 50 in fp32) ----
        #pragma unroll 1
        for (int it = 0; it < 21; it++){
            dm *= 0.5f;
            float tm = tau + dm;
            float fm = 0.f;
            for (int i = l; i < A; i += 32)
                fm += pf<SQ>(fmaxf(sval[i] - tm, 0.f), inv);
            fm = wredsum(fm) - 1.0f;
            if (fm * f_lo >= 0.0f) tau = tm;
        }

        float ss = 0.f;
        for (int i = l; i < A; i += 32)
            ss += pf<SQ>(fmaxf(sval[i] - tau, 0.f), inv);
        const float isum = 1.0f / wredsum(ss);

        __syncwarp();   // zero-fill visible before scatter
        // ---- scatter normalized p over support ----
        for (int i = l; i < A; i += 32){
            float r = sval[i] - tau;
            if (r > 0.0f) prow[sidx[i]] = pf<SQ>(r, inv) * isum;
        }

        // ---- sparse PV over the ~30-40 survivors, 2 dims/lane ----
        float ax = 0.f, ay = 0.f;
        #pragma unroll 2
        for (int i = 0; i < A; i++){
            float r = sval[i] - tau;
            if (r > 0.0f){
                float p = pf<SQ>(r, inv) * isum;
                float2 vv = *(const float2*)(Vb + (size_t)sidx[i]*DIM + 2*l);
                ax += p * vv.x; ay += p * vv.y;
            }
        }
        *(float2*)(outrow + 2*l) = make_float2(ax, ay);
    } else {
        // -------- rare overflow fallback: bisect over gmem row --------
        for (int it = 0; it < 27; it++){
            dm *= 0.5f;
            float tm = tau + dm;
            float fm = 0.f;
            for (int j = l; j < SEQ; j += 32)
                fm += pf<SQ>(fmaxf(prow[j] - tm, 0.f), inv);
            fm = wredsum(fm) - 1.0f;
            if (fm * f_lo >= 0.0f) tau = tm;
        }
        float ss = 0.f;
        for (int j = l; j < SEQ; j += 32)
            ss += pf<SQ>(fmaxf(prow[j] - tau, 0.f), inv);
        float isum = 1.0f / wredsum(ss);

        for (int j = l; j < SEQ; j += 32){
            float r = fmaxf(prow[j] - tau, 0.f);
            prow[j] = pf<SQ>(r, inv) * isum;
        }
        __syncwarp();
        float ax = 0.f, ay = 0.f;
        for (int k = 0; k < SEQ; k++){
            float p = prow[k];
            if (p > 0.0f){
                float2 vv = *(const float2*)(Vb + (size_t)k*DIM + 2*l);
                ax += p * vv.x; ay += p * vv.y;
            }
        }
        *(float2*)(outrow + 2*l) = make_float2(ax, ay);
    }
}

__global__ __launch_bounds__(256) void entmax_pv_warp(const float* __restrict__ V,
        const float* __restrict__ alpha_p, float* __restrict__ out, float* __restrict__ P)
{
    __shared__ float sval[8][CAP];
    __shared__ int   sidx[8][CAP];

    const int w   = threadIdx.x >> 5;
    const int l   = threadIdx.x & 31;
    const size_t row = (size_t)blockIdx.x * 8 + w;
    const int bh  = (int)(row >> 11);

    float* prow = P + row * SEQ;
    const float* Vb = V + (size_t)bh * SEQ * DIM;
    float* outrow = out + row * DIM;

    const float am1 = alpha_p[0] - 1.0f;
    const float inv = 1.0f / am1;
    const bool  sq  = fabsf(inv - 2.0f) < 1e-6f;

    if (sq) row_body<true >(prow, Vb, outrow, row, am1, inv, sval[w], sidx[w], l);
    else    row_body<false>(prow, Vb, outrow, row, am1, inv, sval[w], sidx[w], l);
}

// ================================================================
extern "C" void kernel_launch(void* const* d_in, const int* in_sizes, int n_in,
                              void* d_out, int out_size)
{
    const float* Q     = (const float*)d_in[0];
    const float* K     = (const float*)d_in[1];
    const float* V     = (const float*)d_in[2];
    const float* alpha = (const float*)d_in[3];

    float* out = (float*)d_out;                              // [B,H,S,D]
    float* P   = out + (size_t)NBH * SEQ * DIM;              // [B,H,S,S]

    cudaFuncSetAttribute(qk_kernel, cudaFuncAttributeMaxDynamicSharedMemorySize, 65536);

    dim3 g1(SEQ/128, SEQ/128, NBH);
    qk_kernel<<<g1, 256, 65536>>>(Q, K, alpha, P);

    entmax_pv_warp<<<(NBH * SEQ) / 8, 256>>>(V, alpha, out, P);
}